// round 1
// baseline (speedup 1.0000x reference)
#include <cuda_runtime.h>

#define N_NODES 1024
#define F_DIM   1024
#define H_DIM   512
#define E_EDGES 32768
#define B_GRAPHS 16
#define OUT_DIM 10
#define Z_DIM   (F_DIM + H_DIM)   // 1536
#define EPSB    1e-5f
#define MH_Cf   0.8673250705840776f
#define NEG_HALF_LOG2E (-0.7213475204444817f)
#define LOG2E   1.4426950408889634f
#define INV_SQRT2 0.7071067811865476f

// ---------------- scratch (static device memory; no allocations) ----------------
__device__ __align__(16) float  d_h   [N_NODES * H_DIM];
__device__ __align__(16) float  d_agg [N_NODES * H_DIM];
__device__ __align__(16) float  d_sa  [N_NODES * H_DIM];
__device__ __align__(16) float4 d_wpack[H_DIM * H_DIM];   // [i][o] = {invS, -T*invS, C*Wwav, Wbase}
__device__ __align__(16) float  d_conv[N_NODES * H_DIM];  // wav + base (pre-BN)
__device__ float d_mu [Z_DIM];
__device__ float d_sc [Z_DIM];
__device__ float d_gsum[B_GRAPHS * Z_DIM];
__device__ float d_gcnt[B_GRAPHS];
__device__ float d_pooled[B_GRAPHS * Z_DIM];
__device__ float d_h1 [B_GRAPHS * 512];

__device__ __forceinline__ float ex2f(float x) {
    float r; asm("ex2.approx.ftz.f32 %0, %1;" : "=f"(r) : "f"(x)); return r;
}
__device__ __forceinline__ float fsigmoid(float t) {
    return 1.0f / (1.0f + ex2f(-t * LOG2E));
}

// ---------------- 1. pack transposed weights -----------------------------------
__global__ void k_prep(const float* __restrict__ scale, const float* __restrict__ trans,
                       const float* __restrict__ wavw,  const float* __restrict__ basew) {
    int idx = blockIdx.x * blockDim.x + threadIdx.x;      // idx = o*512 + i
    if (idx >= H_DIM * H_DIM) return;
    int o = idx >> 9, i = idx & 511;
    float invS = 1.0f / scale[idx];
    d_wpack[i * H_DIM + o] = make_float4(invS, -trans[idx] * invS,
                                         MH_Cf * wavw[idx], basew[idx]);
}

// ---------------- 2. DWT attention mix -> h, init agg = h -----------------------
__global__ void k_h(const float* __restrict__ x, const float* __restrict__ watt) {
    int idx = blockIdx.x * blockDim.x + threadIdx.x;      // n*H + j
    int n = idx >> 9, j = idx & 511;
    float2 p = reinterpret_cast<const float2*>(x)[n * (F_DIM / 2) + j]; // (x[n,2j], x[n,2j+1])
    float lo = (p.x + p.y) * INV_SQRT2;
    float hi = (p.x - p.y) * INV_SQRT2;
    float s  = fsigmoid(lo * watt[0] + hi * watt[1]);
    float h  = hi + s * (lo - hi);
    d_h[idx] = h;
    d_agg[idx] = h;
}

// ---------------- 3. zero pooled sums ------------------------------------------
__global__ void k_zero() {
    int t = blockIdx.x * blockDim.x + threadIdx.x;
    if (t < B_GRAPHS * Z_DIM) d_gsum[t] = 0.0f;
    if (t < B_GRAPHS)         d_gcnt[t] = 0.0f;
}

// ---------------- 4. edge scatter: agg[dst] += h[src] ---------------------------
__global__ void __launch_bounds__(128) k_scatter(const int* __restrict__ ei) {
    int e   = blockIdx.x;
    int src = ei[e];
    int dst = ei[E_EDGES + e];
    float4 v = reinterpret_cast<const float4*>(d_h + src * H_DIM)[threadIdx.x];
    float* ad = d_agg + dst * H_DIM + threadIdx.x * 4;
    atomicAdd(ad + 0, v.x);
    atomicAdd(ad + 1, v.y);
    atomicAdd(ad + 2, v.z);
    atomicAdd(ad + 3, v.w);
}

// ---------------- 5. silu(agg) ---------------------------------------------------
__global__ void k_silu() {
    int idx = blockIdx.x * blockDim.x + threadIdx.x;
    float a = d_agg[idx];
    d_sa[idx] = a * fsigmoid(a);
}

// ---------------- 6. main loop: wav + base --------------------------------------
// block: 128 threads (one o each of a 128-wide o-strip), RN=8 nodes per block.
__global__ void __launch_bounds__(128) k_wavbase() {
    __shared__ float2 sh[8 * H_DIM];                      // [n][i] = {agg, silu(agg)}
    int o  = blockIdx.x * 128 + threadIdx.x;
    int n0 = blockIdx.y * 8;

    for (int idx = threadIdx.x; idx < 8 * H_DIM; idx += 128) {
        int n = idx >> 9, i = idx & 511;
        sh[(n << 9) | i] = make_float2(d_agg[(n0 + n) * H_DIM + i],
                                       d_sa [(n0 + n) * H_DIM + i]);
    }
    __syncthreads();

    float accw[8], accb[8];
#pragma unroll
    for (int n = 0; n < 8; n++) { accw[n] = 0.0f; accb[n] = 0.0f; }

    for (int i = 0; i < H_DIM; i++) {
        float4 w = __ldg(&d_wpack[i * H_DIM + o]);        // {invS, -T*invS, C*Ww, Wb}
#pragma unroll
        for (int n = 0; n < 8; n++) {
            float2 as = sh[(n << 9) | i];
            float u  = fmaf(as.x, w.x, w.y);
            float u2 = u * u;
            float e  = ex2f(u2 * NEG_HALF_LOG2E);
            float wv = w.z * u2;
            accw[n] = fmaf(w.z - wv, e, accw[n]);         // C*W*(1-u2)*exp(-u2/2)
            accb[n] = fmaf(as.y, w.w, accb[n]);           // silu(agg) @ Wb^T
        }
    }
#pragma unroll
    for (int n = 0; n < 8; n++)
        d_conv[(n0 + n) * H_DIM + o] = accw[n] + accb[n];
}

// ---------------- 7. per-column stats (bn chains folded to affine) ---------------
__global__ void k_colstats(const float* __restrict__ x) {
    __shared__ float ssum[8][32], ssq[8][32];
    int c = threadIdx.x, r = threadIdx.y;
    int j = blockIdx.x * 32 + c;
    const float* base; int stride, col;
    if (j < F_DIM) { base = x;      stride = F_DIM; col = j; }
    else           { base = d_conv; stride = H_DIM; col = j - F_DIM; }
    float s = 0.0f, q = 0.0f;
    for (int n = r; n < N_NODES; n += 8) {
        float v = base[n * stride + col];
        s += v; q = fmaf(v, v, q);
    }
    ssum[r][c] = s; ssq[r][c] = q;
    __syncthreads();
    if (r == 0) {
#pragma unroll
        for (int rr = 1; rr < 8; rr++) { s += ssum[rr][c]; q += ssq[rr][c]; }
        float mu  = s * (1.0f / N_NODES);
        float var = fmaxf(q * (1.0f / N_NODES) - mu * mu, 0.0f);
        float sc;
        if (j < F_DIM) {
            sc = rsqrtf(var + EPSB);                      // single bn on x cols
        } else {                                          // bn(bn(bn(.))) on conv cols
            float a1 = rsqrtf(var + EPSB);
            float v1 = var / (var + EPSB);
            float a2 = rsqrtf(v1 + EPSB);
            float v2 = v1 / (v1 + EPSB);
            float a3 = rsqrtf(v2 + EPSB);
            sc = a1 * a2 * a3;
        }
        d_mu[j] = mu; d_sc[j] = sc;
    }
}

// ---------------- 8. segment sums (raw values; norm folded post-pool) -----------
__global__ void __launch_bounds__(384) k_pool(const float* __restrict__ x,
                                              const int* __restrict__ batch) {
    int n = blockIdx.x;
    int b = batch[n];
    int t = threadIdx.x;
#pragma unroll
    for (int q = 0; q < 4; q++) {
        int j = t * 4 + q;
        float v = (j < F_DIM) ? x[n * F_DIM + j] : d_conv[n * H_DIM + (j - F_DIM)];
        atomicAdd(&d_gsum[b * Z_DIM + j], v);
    }
    if (t == 0) atomicAdd(&d_gcnt[b], 1.0f);
}

// ---------------- 9. pooled = (mean - mu) * s ------------------------------------
__global__ void k_poolfinal() {
    int t = blockIdx.x * blockDim.x + threadIdx.x;
    if (t >= B_GRAPHS * Z_DIM) return;
    int b = t / Z_DIM, j = t % Z_DIM;
    float cnt = fmaxf(d_gcnt[b], 1.0f);
    d_pooled[t] = (d_gsum[t] / cnt - d_mu[j]) * d_sc[j];
}

// ---------------- 10. fc1 + relu (warp per output neuron) ------------------------
__global__ void __launch_bounds__(1024) k_fc1(const float* __restrict__ w,
                                              const float* __restrict__ bias) {
    int warp = (blockIdx.x * blockDim.x + threadIdx.x) >> 5;  // 0..511 = o
    int lane = threadIdx.x & 31;
    float acc[B_GRAPHS];
#pragma unroll
    for (int b = 0; b < B_GRAPHS; b++) acc[b] = 0.0f;
    for (int k0 = 0; k0 < Z_DIM; k0 += 32) {
        float wv = w[warp * Z_DIM + k0 + lane];
#pragma unroll
        for (int b = 0; b < B_GRAPHS; b++)
            acc[b] = fmaf(wv, d_pooled[b * Z_DIM + k0 + lane], acc[b]);
    }
#pragma unroll
    for (int b = 0; b < B_GRAPHS; b++) {
        float s = acc[b];
        s += __shfl_xor_sync(0xffffffffu, s, 16);
        s += __shfl_xor_sync(0xffffffffu, s, 8);
        s += __shfl_xor_sync(0xffffffffu, s, 4);
        s += __shfl_xor_sync(0xffffffffu, s, 2);
        s += __shfl_xor_sync(0xffffffffu, s, 1);
        acc[b] = s;
    }
    if (lane == 0) {
        float bi = bias[warp];
#pragma unroll
        for (int b = 0; b < B_GRAPHS; b++)
            d_h1[b * 512 + warp] = fmaxf(acc[b] + bi, 0.0f);
    }
}

// ---------------- 11. fc2 ---------------------------------------------------------
__global__ void k_fc2(const float* __restrict__ w, const float* __restrict__ bias,
                      float* __restrict__ out) {
    int t = threadIdx.x;
    if (t >= B_GRAPHS * OUT_DIM) return;
    int b = t / OUT_DIM, k = t % OUT_DIM;
    float s = bias[k];
    for (int o = 0; o < 512; o++)
        s = fmaf(d_h1[b * 512 + o], w[k * 512 + o], s);
    out[b * OUT_DIM + k] = s;
}

// ---------------- launch ----------------------------------------------------------
extern "C" void kernel_launch(void* const* d_in, const int* in_sizes, int n_in,
                              void* d_out, int out_size) {
    const float* x      = (const float*)d_in[0];
    const float* w_att  = (const float*)d_in[1];
    const float* wscale = (const float*)d_in[2];
    const float* wtrans = (const float*)d_in[3];
    const float* wwav   = (const float*)d_in[4];
    const float* wbase  = (const float*)d_in[5];
    const float* fc1w   = (const float*)d_in[6];
    const float* fc1b   = (const float*)d_in[7];
    const float* fc2w   = (const float*)d_in[8];
    const float* fc2b   = (const float*)d_in[9];
    const int*   eidx   = (const int*)d_in[10];
    const int*   batch  = (const int*)d_in[11];
    float*       out    = (float*)d_out;

    k_prep<<<(H_DIM * H_DIM + 255) / 256, 256>>>(wscale, wtrans, wwav, wbase);
    k_h<<<(N_NODES * H_DIM + 255) / 256, 256>>>(x, w_att);
    k_zero<<<(B_GRAPHS * Z_DIM + 255) / 256, 256>>>();
    k_scatter<<<E_EDGES, 128>>>(eidx);
    k_silu<<<(N_NODES * H_DIM + 255) / 256, 256>>>();
    k_wavbase<<<dim3(H_DIM / 128, N_NODES / 8), 128>>>();
    k_colstats<<<Z_DIM / 32, dim3(32, 8)>>>(x);
    k_pool<<<N_NODES, 384>>>(x, batch);
    k_poolfinal<<<(B_GRAPHS * Z_DIM + 255) / 256, 256>>>();
    k_fc1<<<16, 1024>>>(fc1w, fc1b);
    k_fc2<<<1, 192>>>(fc2w, fc2b, out);
}

// round 2
// speedup vs baseline: 1.2636x; 1.2636x over previous
#include <cuda_runtime.h>

#define N_NODES 1024
#define F_DIM   1024
#define H_DIM   512
#define E_EDGES 32768
#define B_GRAPHS 16
#define OUT_DIM 10
#define Z_DIM   (F_DIM + H_DIM)   // 1536
#define EPSB    1e-5f
#define MH_Cf   0.8673250705840776f
#define NEG_HALF_LOG2E (-0.7213475204444817f)
#define LOG2E   1.4426950408889634f
#define INV_SQRT2 0.7071067811865476f
#define RN 16                      // nodes per wavbase block

// ---------------- scratch (static device memory; no allocations) ----------------
__device__ __align__(16) float  d_h   [N_NODES * H_DIM];
__device__ __align__(16) float  d_agg [N_NODES * H_DIM];
__device__ __align__(16) float4 d_wpack[H_DIM * H_DIM];   // [i][o] = {invS, -T*invS, C*Wwav, Wbase}
__device__ __align__(16) float  d_conv[N_NODES * H_DIM];  // wav + base (pre-BN)
__device__ float d_mu [Z_DIM];
__device__ float d_sc [Z_DIM];
__device__ float d_gsum[B_GRAPHS * Z_DIM];
__device__ float d_gcnt[B_GRAPHS];
__device__ float d_pooled[B_GRAPHS * Z_DIM];
__device__ float d_h1 [B_GRAPHS * 512];
// CSR scratch
__device__ int d_deg [N_NODES];
__device__ int d_off [N_NODES + 1];
__device__ int d_fill[N_NODES];
__device__ int d_elist[E_EDGES];

__device__ __forceinline__ float ex2f(float x) {
    float r; asm("ex2.approx.ftz.f32 %0, %1;" : "=f"(r) : "f"(x)); return r;
}
__device__ __forceinline__ float fsigmoid(float t) {
    return 1.0f / (1.0f + ex2f(-t * LOG2E));
}

// ---- f32x2 packed-math helpers (sm_103a) ----
typedef unsigned long long u64;
__device__ __forceinline__ u64 pack2(float lo, float hi) {
    u64 r; asm("mov.b64 %0, {%1, %2};" : "=l"(r) : "f"(lo), "f"(hi)); return r;
}
__device__ __forceinline__ void unpack2(u64 v, float& lo, float& hi) {
    asm("mov.b64 {%0, %1}, %2;" : "=f"(lo), "=f"(hi) : "l"(v));
}
__device__ __forceinline__ u64 fma2(u64 a, u64 b, u64 c) {
    u64 d; asm("fma.rn.f32x2 %0, %1, %2, %3;" : "=l"(d) : "l"(a), "l"(b), "l"(c)); return d;
}
__device__ __forceinline__ u64 mul2(u64 a, u64 b) {
    u64 d; asm("mul.rn.f32x2 %0, %1, %2;" : "=l"(d) : "l"(a), "l"(b)); return d;
}

// ---------------- 1. pack transposed weights -----------------------------------
__global__ void k_prep(const float* __restrict__ scale, const float* __restrict__ trans,
                       const float* __restrict__ wavw,  const float* __restrict__ basew) {
    int idx = blockIdx.x * blockDim.x + threadIdx.x;      // idx = o*512 + i
    if (idx >= H_DIM * H_DIM) return;
    int o = idx >> 9, i = idx & 511;
    float invS = 1.0f / scale[idx];
    d_wpack[i * H_DIM + o] = make_float4(invS, -trans[idx] * invS,
                                         MH_Cf * wavw[idx], basew[idx]);
}

// ---------------- 2. DWT attention mix -> h ------------------------------------
__global__ void k_h(const float* __restrict__ x, const float* __restrict__ watt) {
    int idx = blockIdx.x * blockDim.x + threadIdx.x;      // n*H + j
    int n = idx >> 9, j = idx & 511;
    float2 p = reinterpret_cast<const float2*>(x)[n * (F_DIM / 2) + j];
    float lo = (p.x + p.y) * INV_SQRT2;
    float hi = (p.x - p.y) * INV_SQRT2;
    float s  = fsigmoid(lo * watt[0] + hi * watt[1]);
    d_h[idx] = hi + s * (lo - hi);
}

// ---------------- 3. zero scratch -----------------------------------------------
__global__ void k_zero() {
    int t = blockIdx.x * blockDim.x + threadIdx.x;
    if (t < B_GRAPHS * Z_DIM) d_gsum[t] = 0.0f;
    if (t < B_GRAPHS)         d_gcnt[t] = 0.0f;
    if (t < N_NODES)          d_deg[t]  = 0;
}

// ---------------- 4a. degree histogram ------------------------------------------
__global__ void k_deg(const int* __restrict__ ei) {
    int e = blockIdx.x * blockDim.x + threadIdx.x;
    if (e < E_EDGES) atomicAdd(&d_deg[ei[E_EDGES + e]], 1);
}

// ---------------- 4b. exclusive scan (single block) ------------------------------
__global__ void __launch_bounds__(N_NODES) k_scan() {
    __shared__ int s[N_NODES];
    int t = threadIdx.x;
    int v = d_deg[t];
    s[t] = v;
    __syncthreads();
    for (int off = 1; off < N_NODES; off <<= 1) {
        int add = (t >= off) ? s[t - off] : 0;
        __syncthreads();
        s[t] += add;
        __syncthreads();
    }
    int excl = s[t] - v;
    d_off[t]  = excl;
    d_fill[t] = excl;
    if (t == N_NODES - 1) d_off[N_NODES] = s[t];
}

// ---------------- 4c. fill edge lists --------------------------------------------
__global__ void k_fill(const int* __restrict__ ei) {
    int e = blockIdx.x * blockDim.x + threadIdx.x;
    if (e < E_EDGES) {
        int dst = ei[E_EDGES + e];
        int pos = atomicAdd(&d_fill[dst], 1);
        d_elist[pos] = ei[e];
    }
}

// ---------------- 4d. gather: agg[n] = h[n] + sum_{e:dst=n} h[src] ---------------
__global__ void __launch_bounds__(128) k_gather() {
    __shared__ int se[128];
    int n = blockIdx.x, t = threadIdx.x;
    int beg = d_off[n], end = d_off[n + 1];
    float4 acc = reinterpret_cast<const float4*>(d_h + n * H_DIM)[t];
    for (int t0 = beg; t0 < end; t0 += 128) {
        int cnt = min(128, end - t0);
        if (t < cnt) se[t] = d_elist[t0 + t];
        __syncthreads();
        for (int k = 0; k < cnt; k++) {
            float4 v = reinterpret_cast<const float4*>(d_h + se[k] * H_DIM)[t];
            acc.x += v.x; acc.y += v.y; acc.z += v.z; acc.w += v.w;
        }
        __syncthreads();
    }
    reinterpret_cast<float4*>(d_agg + n * H_DIM)[t] = acc;
}

// ---------------- 5. main loop: wav + base (packed f32x2) ------------------------
// block: 128 threads (one o each), RN=16 nodes, smem = 512 i x 8 pairs x 16B = 64KB
__global__ void __launch_bounds__(128) k_wavbase() {
    __shared__ ulonglong2 s_pair[H_DIM * (RN / 2)];   // [i][p] = {agg01, sa01}
    float* s_f = reinterpret_cast<float*>(s_pair);
    int o  = blockIdx.x * 128 + threadIdx.x;
    int n0 = blockIdx.y * RN;

    // stage agg + silu(agg), transposed to node-pair-contiguous layout
    for (int idx = threadIdx.x; idx < (H_DIM / 4) * RN; idx += 128) {
        int c = idx / RN;          // i-chunk (4 i's)
        int n = idx % RN;
        float4 a4 = *reinterpret_cast<const float4*>(&d_agg[(n0 + n) * H_DIM + c * 4]);
        int p = n >> 1, half = n & 1;
        float av[4] = {a4.x, a4.y, a4.z, a4.w};
#pragma unroll
        for (int d = 0; d < 4; d++) {
            int i = c * 4 + d;
            float a  = av[d];
            float sa = a * fsigmoid(a);
            int base = (i * (RN / 2) + p) * 4;
            s_f[base + half]     = a;
            s_f[base + 2 + half] = sa;
        }
    }
    __syncthreads();

    u64 accw[RN / 2], accb[RN / 2];
#pragma unroll
    for (int p = 0; p < RN / 2; p++) { accw[p] = 0ull; accb[p] = 0ull; }
    const u64 cc2 = pack2(NEG_HALF_LOG2E, NEG_HALF_LOG2E);

    for (int i = 0; i < H_DIM; i++) {
        float4 w = __ldg(&d_wpack[i * H_DIM + o]);    // {invS, -T*invS, C*Ww, Wb}
        u64 wx2 = pack2(w.x, w.x);
        u64 wy2 = pack2(w.y, w.y);
        float nz = -w.z;
        u64 nwz2 = pack2(nz, nz);
        u64 wz2  = pack2(w.z, w.z);
        u64 ww2  = pack2(w.w, w.w);
        const ulonglong2* row = &s_pair[i * (RN / 2)];
#pragma unroll
        for (int p = 0; p < RN / 2; p++) {
            ulonglong2 v = row[p];
            u64 u   = fma2(v.x, wx2, wy2);            // (agg - T)/S
            u64 t   = mul2(u, u);
            u64 arg = mul2(t, cc2);
            float alo, ahi; unpack2(arg, alo, ahi);
            u64 e   = pack2(ex2f(alo), ex2f(ahi));    // exp(-u^2/2)
            u64 g   = fma2(t, nwz2, wz2);             // C*W*(1 - u^2)
            accw[p] = fma2(g, e, accw[p]);
            accb[p] = fma2(v.y, ww2, accb[p]);        // silu(agg) @ Wb^T
        }
    }
#pragma unroll
    for (int p = 0; p < RN / 2; p++) {
        float w0, w1, b0, b1;
        unpack2(accw[p], w0, w1);
        unpack2(accb[p], b0, b1);
        d_conv[(n0 + 2 * p)     * H_DIM + o] = w0 + b0;
        d_conv[(n0 + 2 * p + 1) * H_DIM + o] = w1 + b1;
    }
}

// ---------------- 6. per-column stats (bn chains folded to affine) ---------------
__global__ void k_colstats(const float* __restrict__ x) {
    __shared__ float ssum[8][32], ssq[8][32];
    int c = threadIdx.x, r = threadIdx.y;
    int j = blockIdx.x * 32 + c;
    const float* base; int stride, col;
    if (j < F_DIM) { base = x;      stride = F_DIM; col = j; }
    else           { base = d_conv; stride = H_DIM; col = j - F_DIM; }
    float s = 0.0f, q = 0.0f;
    for (int n = r; n < N_NODES; n += 8) {
        float v = base[n * stride + col];
        s += v; q = fmaf(v, v, q);
    }
    ssum[r][c] = s; ssq[r][c] = q;
    __syncthreads();
    if (r == 0) {
#pragma unroll
        for (int rr = 1; rr < 8; rr++) { s += ssum[rr][c]; q += ssq[rr][c]; }
        float mu  = s * (1.0f / N_NODES);
        float var = fmaxf(q * (1.0f / N_NODES) - mu * mu, 0.0f);
        float sc;
        if (j < F_DIM) {
            sc = rsqrtf(var + EPSB);
        } else {
            float a1 = rsqrtf(var + EPSB);
            float v1 = var / (var + EPSB);
            float a2 = rsqrtf(v1 + EPSB);
            float v2 = v1 / (v1 + EPSB);
            float a3 = rsqrtf(v2 + EPSB);
            sc = a1 * a2 * a3;
        }
        d_mu[j] = mu; d_sc[j] = sc;
    }
}

// ---------------- 7. segment sums (raw values; norm folded post-pool) -----------
__global__ void __launch_bounds__(384) k_pool(const float* __restrict__ x,
                                              const int* __restrict__ batch) {
    int n = blockIdx.x;
    int b = batch[n];
    int t = threadIdx.x;
#pragma unroll
    for (int q = 0; q < 4; q++) {
        int j = t * 4 + q;
        float v = (j < F_DIM) ? x[n * F_DIM + j] : d_conv[n * H_DIM + (j - F_DIM)];
        atomicAdd(&d_gsum[b * Z_DIM + j], v);
    }
    if (t == 0) atomicAdd(&d_gcnt[b], 1.0f);
}

// ---------------- 8. pooled = (mean - mu) * s ------------------------------------
__global__ void k_poolfinal() {
    int t = blockIdx.x * blockDim.x + threadIdx.x;
    if (t >= B_GRAPHS * Z_DIM) return;
    int b = t / Z_DIM, j = t % Z_DIM;
    float cnt = fmaxf(d_gcnt[b], 1.0f);
    d_pooled[t] = (d_gsum[t] / cnt - d_mu[j]) * d_sc[j];
}

// ---------------- 9. fc1 + relu (warp per output neuron) ------------------------
__global__ void __launch_bounds__(1024) k_fc1(const float* __restrict__ w,
                                              const float* __restrict__ bias) {
    int warp = (blockIdx.x * blockDim.x + threadIdx.x) >> 5;  // 0..511 = o
    int lane = threadIdx.x & 31;
    float acc[B_GRAPHS];
#pragma unroll
    for (int b = 0; b < B_GRAPHS; b++) acc[b] = 0.0f;
    for (int k0 = 0; k0 < Z_DIM; k0 += 32) {
        float wv = w[warp * Z_DIM + k0 + lane];
#pragma unroll
        for (int b = 0; b < B_GRAPHS; b++)
            acc[b] = fmaf(wv, d_pooled[b * Z_DIM + k0 + lane], acc[b]);
    }
#pragma unroll
    for (int b = 0; b < B_GRAPHS; b++) {
        float s = acc[b];
        s += __shfl_xor_sync(0xffffffffu, s, 16);
        s += __shfl_xor_sync(0xffffffffu, s, 8);
        s += __shfl_xor_sync(0xffffffffu, s, 4);
        s += __shfl_xor_sync(0xffffffffu, s, 2);
        s += __shfl_xor_sync(0xffffffffu, s, 1);
        acc[b] = s;
    }
    if (lane == 0) {
        float bi = bias[warp];
#pragma unroll
        for (int b = 0; b < B_GRAPHS; b++)
            d_h1[b * 512 + warp] = fmaxf(acc[b] + bi, 0.0f);
    }
}

// ---------------- 10. fc2 ---------------------------------------------------------
__global__ void k_fc2(const float* __restrict__ w, const float* __restrict__ bias,
                      float* __restrict__ out) {
    int t = threadIdx.x;
    if (t >= B_GRAPHS * OUT_DIM) return;
    int b = t / OUT_DIM, k = t % OUT_DIM;
    float s = bias[k];
    for (int o = 0; o < 512; o++)
        s = fmaf(d_h1[b * 512 + o], w[k * 512 + o], s);
    out[b * OUT_DIM + k] = s;
}

// ---------------- launch ----------------------------------------------------------
extern "C" void kernel_launch(void* const* d_in, const int* in_sizes, int n_in,
                              void* d_out, int out_size) {
    const float* x      = (const float*)d_in[0];
    const float* w_att  = (const float*)d_in[1];
    const float* wscale = (const float*)d_in[2];
    const float* wtrans = (const float*)d_in[3];
    const float* wwav   = (const float*)d_in[4];
    const float* wbase  = (const float*)d_in[5];
    const float* fc1w   = (const float*)d_in[6];
    const float* fc1b   = (const float*)d_in[7];
    const float* fc2w   = (const float*)d_in[8];
    const float* fc2b   = (const float*)d_in[9];
    const int*   eidx   = (const int*)d_in[10];
    const int*   batch  = (const int*)d_in[11];
    float*       out    = (float*)d_out;

    k_prep<<<(H_DIM * H_DIM + 255) / 256, 256>>>(wscale, wtrans, wwav, wbase);
    k_zero<<<(B_GRAPHS * Z_DIM + 255) / 256, 256>>>();
    k_deg<<<(E_EDGES + 255) / 256, 256>>>(eidx);
    k_scan<<<1, N_NODES>>>();
    k_fill<<<(E_EDGES + 255) / 256, 256>>>(eidx);
    k_h<<<(N_NODES * H_DIM + 255) / 256, 256>>>(x, w_att);
    k_gather<<<N_NODES, 128>>>();
    k_wavbase<<<dim3(H_DIM / 128, N_NODES / RN), 128>>>();
    k_colstats<<<Z_DIM / 32, dim3(32, 8)>>>(x);
    k_pool<<<N_NODES, 384>>>(x, batch);
    k_poolfinal<<<(B_GRAPHS * Z_DIM + 255) / 256, 256>>>();
    k_fc1<<<16, 1024>>>(fc1w, fc1b);
    k_fc2<<<1, 192>>>(fc2w, fc2b, out);
}